// round 1
// baseline (speedup 1.0000x reference)
#include <cuda_runtime.h>
#include <math.h>

// Problem constants: B=4, SEQ=2048 -> M=8192 rows; D_MODEL=768; N_STATE=16.
#define M_TOTAL 8192
#define D 768
#define NSTATE 16

// Per-row scalar s[m] = dot(x_m@W2 + b2, x_m@W3 + b3). Device scratch (no allocs allowed).
__device__ float g_s[M_TOTAL];

// ---------------------------------------------------------------------------
// Kernel 1: dual tiny projection + dot. 4 threads per row, each covering a
// 192-wide K chunk, vectorized float4 loads of W2/W3 rows, warp-shuffle reduce.
// ---------------------------------------------------------------------------
__global__ void __launch_bounds__(256) s6_s_kernel(
    const float* __restrict__ x,
    const float* __restrict__ W2, const float* __restrict__ b2,
    const float* __restrict__ W3, const float* __restrict__ b3)
{
    int gtid = blockIdx.x * blockDim.x + threadIdx.x;
    int row   = gtid >> 2;
    int chunk = gtid & 3;
    if (row >= M_TOTAL) return;

    const float* xr = x + (size_t)row * D;

    float accB[NSTATE], accC[NSTATE];
#pragma unroll
    for (int n = 0; n < NSTATE; n++) { accB[n] = 0.f; accC[n] = 0.f; }

    const int kc = D / 4;            // 192
    const int k0 = chunk * kc;

    for (int k = k0; k < k0 + kc; k++) {
        float xv = __ldg(xr + k);
        const float4* w2r = (const float4*)(W2 + (size_t)k * NSTATE);
        const float4* w3r = (const float4*)(W3 + (size_t)k * NSTATE);
#pragma unroll
        for (int q = 0; q < 4; q++) {
            float4 w2 = __ldg(w2r + q);
            float4 w3 = __ldg(w3r + q);
            accB[q*4+0] = fmaf(xv, w2.x, accB[q*4+0]);
            accB[q*4+1] = fmaf(xv, w2.y, accB[q*4+1]);
            accB[q*4+2] = fmaf(xv, w2.z, accB[q*4+2]);
            accB[q*4+3] = fmaf(xv, w2.w, accB[q*4+3]);
            accC[q*4+0] = fmaf(xv, w3.x, accC[q*4+0]);
            accC[q*4+1] = fmaf(xv, w3.y, accC[q*4+1]);
            accC[q*4+2] = fmaf(xv, w3.z, accC[q*4+2]);
            accC[q*4+3] = fmaf(xv, w3.w, accC[q*4+3]);
        }
    }

    // Reduce across the 4 consecutive chunk-lanes of this row.
#pragma unroll
    for (int off = 1; off < 4; off <<= 1) {
#pragma unroll
        for (int n = 0; n < NSTATE; n++) {
            accB[n] += __shfl_xor_sync(0xffffffffu, accB[n], off);
            accC[n] += __shfl_xor_sync(0xffffffffu, accC[n], off);
        }
    }

    if (chunk == 0) {
        float s = 0.f;
#pragma unroll
        for (int n = 0; n < NSTATE; n++)
            s = fmaf(accB[n] + __ldg(b2 + n), accC[n] + __ldg(b3 + n), s);
        g_s[row] = s;
    }
}

// ---------------------------------------------------------------------------
// Kernel 2: fused SGEMM  y[m,n] = x[m,n] * softplus((x@W1)[m,n] + b1[n]) * s[m]
// 128x128 block tile, BK=8, 256 threads, 8x8 per-thread micro-tile.
// ---------------------------------------------------------------------------
#define BM 128
#define BN 128
#define BK 8
#define TM 8
#define TN 8

__global__ void __launch_bounds__(256) s6_gemm_fused(
    const float* __restrict__ x,
    const float* __restrict__ W1, const float* __restrict__ b1,
    float* __restrict__ y)
{
    __shared__ float As[BK][BM];   // transposed A tile
    __shared__ float Bs[BK][BN];

    const int tid = threadIdx.x;
    const int tx  = tid % 16;      // column group
    const int ty  = tid / 16;      // row group
    const int row0 = blockIdx.y * BM;
    const int col0 = blockIdx.x * BN;

    // A-tile load mapping: 256 threads x float4 = 1024 floats = 128x8
    const int arow = tid >> 1;          // 0..127
    const int acol = (tid & 1) * 4;     // 0 or 4
    // B-tile load mapping: 8 rows x 128 cols
    const int brow = tid >> 5;          // 0..7
    const int bcol = (tid & 31) * 4;    // 0..124

    const float* Aptr = x  + (size_t)(row0 + arow) * D + acol;
    const float* Bptr = W1 + (size_t)brow * D + col0 + bcol;

    float acc[TM][TN];
#pragma unroll
    for (int i = 0; i < TM; i++)
#pragma unroll
        for (int j = 0; j < TN; j++) acc[i][j] = 0.f;

    for (int k0 = 0; k0 < D; k0 += BK) {
        float4 av = *(const float4*)(Aptr + k0);
        float4 bv = *(const float4*)(Bptr + (size_t)k0 * D);

        As[acol + 0][arow] = av.x;
        As[acol + 1][arow] = av.y;
        As[acol + 2][arow] = av.z;
        As[acol + 3][arow] = av.w;
        *(float4*)&Bs[brow][bcol] = bv;
        __syncthreads();

#pragma unroll
        for (int kk = 0; kk < BK; kk++) {
            float a[TM], b[TN];
#pragma unroll
            for (int i = 0; i < TM; i += 4)
                *(float4*)&a[i] = *(const float4*)&As[kk][ty * TM + i];
#pragma unroll
            for (int j = 0; j < TN; j += 4)
                *(float4*)&b[j] = *(const float4*)&Bs[kk][tx * TN + j];
#pragma unroll
            for (int i = 0; i < TM; i++)
#pragma unroll
                for (int j = 0; j < TN; j++)
                    acc[i][j] = fmaf(a[i], b[j], acc[i][j]);
        }
        __syncthreads();
    }

    // Epilogue: softplus + x * s scaling, vectorized float4 stores.
#pragma unroll
    for (int i = 0; i < TM; i++) {
        const int m = row0 + ty * TM + i;
        const float sm = g_s[m];
        const float* xrow = x + (size_t)m * D;
        float* yrow = y + (size_t)m * D;
#pragma unroll
        for (int j = 0; j < TN; j += 4) {
            const int n = col0 + tx * TN + j;
            float4 bb = *(const float4*)(b1 + n);
            float4 xv = *(const float4*)(xrow + n);
            float z0 = acc[i][j + 0] + bb.x;
            float z1 = acc[i][j + 1] + bb.y;
            float z2 = acc[i][j + 2] + bb.z;
            float z3 = acc[i][j + 3] + bb.w;
            float sp0 = (z0 > 20.f) ? z0 : log1pf(expf(z0));
            float sp1 = (z1 > 20.f) ? z1 : log1pf(expf(z1));
            float sp2 = (z2 > 20.f) ? z2 : log1pf(expf(z2));
            float sp3 = (z3 > 20.f) ? z3 : log1pf(expf(z3));
            float4 out;
            out.x = xv.x * sp0 * sm;
            out.y = xv.y * sp1 * sm;
            out.z = xv.z * sp2 * sm;
            out.w = xv.w * sp3 * sm;
            *(float4*)(yrow + n) = out;
        }
    }
}

// ---------------------------------------------------------------------------
// Launch. Inputs (metadata order): x, W1, b1, W2, b2, W3, b3, A (A unused: h0=0).
// ---------------------------------------------------------------------------
extern "C" void kernel_launch(void* const* d_in, const int* in_sizes, int n_in,
                              void* d_out, int out_size)
{
    const float* x  = (const float*)d_in[0];
    const float* W1 = (const float*)d_in[1];
    const float* b1 = (const float*)d_in[2];
    const float* W2 = (const float*)d_in[3];
    const float* b2 = (const float*)d_in[4];
    const float* W3 = (const float*)d_in[5];
    const float* b3 = (const float*)d_in[6];
    float* y = (float*)d_out;

    // s[m] per row: 4 threads/row -> 32768 threads.
    s6_s_kernel<<<(M_TOTAL * 4) / 256, 256>>>(x, W2, b2, W3, b3);

    // Fused GEMM + softplus + scale.
    dim3 grid(D / BN, M_TOTAL / BM);   // (6, 64)
    s6_gemm_fused<<<grid, 256>>>(x, W1, b1, y);
}

// round 3
// speedup vs baseline: 2.7820x; 2.7820x over previous
#include <cuda_runtime.h>
#include <cuda_bf16.h>
#include <stdint.h>
#include <math.h>

#define M_TOTAL 8192
#define D 768
#define NSTATE 16

// GEMM tiling
#define BM 128
#define BN 128
#define BK 64
#define NSTG 3
#define KTILES 36                 // 3 terms * (768/64)
#define ASTAGE (BM * BK * 2)      // 16384 B
#define STAGE_BYTES (2 * ASTAGE)  // 32768 B
#define GEMM_SMEM (NSTG * STAGE_BYTES)  // 98304 B

// ---------------- device scratch (no allocs allowed) ----------------
__device__ __align__(16) __nv_bfloat16 g_x_hi[M_TOTAL * D];
__device__ __align__(16) __nv_bfloat16 g_x_lo[M_TOTAL * D];
__device__ __align__(16) __nv_bfloat16 g_wt_hi[D * D];   // W1^T: [n][k]
__device__ __align__(16) __nv_bfloat16 g_wt_lo[D * D];
__device__ float g_s[M_TOTAL];

// ---------------- helpers ----------------
__device__ __forceinline__ uint32_t smem_u32(const void* p) {
    uint32_t a;
    asm("{ .reg .u64 t; cvta.to.shared.u64 t, %1; cvt.u32.u64 %0, t; }"
        : "=r"(a) : "l"(p));
    return a;
}
#define SW128(o) ((o) ^ (((o) >> 3) & 0x70))

__device__ __forceinline__ void cp_async16(uint32_t dst, const void* src) {
    asm volatile("cp.async.cg.shared.global [%0], [%1], 16;" :: "r"(dst), "l"(src));
}

__device__ __forceinline__ void ldmatrix_x4(uint32_t& r0, uint32_t& r1,
                                            uint32_t& r2, uint32_t& r3,
                                            uint32_t addr) {
    asm volatile("ldmatrix.sync.aligned.m8n8.x4.shared.b16 {%0,%1,%2,%3}, [%4];"
                 : "=r"(r0), "=r"(r1), "=r"(r2), "=r"(r3) : "r"(addr));
}

__device__ __forceinline__ void mma_bf16(float* c,
                                         uint32_t a0, uint32_t a1, uint32_t a2, uint32_t a3,
                                         uint32_t b0, uint32_t b1) {
    asm volatile("mma.sync.aligned.m16n8k16.row.col.f32.bf16.bf16.f32 "
                 "{%0,%1,%2,%3}, {%4,%5,%6,%7}, {%8,%9}, {%0,%1,%2,%3};"
                 : "+f"(c[0]), "+f"(c[1]), "+f"(c[2]), "+f"(c[3])
                 : "r"(a0), "r"(a1), "r"(a2), "r"(a3), "r"(b0), "r"(b1));
}

__device__ __forceinline__ float softplus_f(float z) {
    if (z > 20.f) return z;
    return log1pf(__expf(z));
}

// ---------------------------------------------------------------------------
// split conversions
// ---------------------------------------------------------------------------
__global__ void __launch_bounds__(256) k_split_x(const float4* __restrict__ x4) {
    int i = blockIdx.x * 256 + threadIdx.x;            // 0 .. M*D/4-1
    float4 v = x4[i];
    __nv_bfloat16 h0 = __float2bfloat16(v.x);
    __nv_bfloat16 h1 = __float2bfloat16(v.y);
    __nv_bfloat16 h2 = __float2bfloat16(v.z);
    __nv_bfloat16 h3 = __float2bfloat16(v.w);
    __nv_bfloat16 l0 = __float2bfloat16(v.x - __bfloat162float(h0));
    __nv_bfloat16 l1 = __float2bfloat16(v.y - __bfloat162float(h1));
    __nv_bfloat16 l2 = __float2bfloat16(v.z - __bfloat162float(h2));
    __nv_bfloat16 l3 = __float2bfloat16(v.w - __bfloat162float(h3));
    __nv_bfloat162* ph = (__nv_bfloat162*)g_x_hi;
    __nv_bfloat162* pl = (__nv_bfloat162*)g_x_lo;
    ph[i * 2 + 0] = __halves2bfloat162(h0, h1);
    ph[i * 2 + 1] = __halves2bfloat162(h2, h3);
    pl[i * 2 + 0] = __halves2bfloat162(l0, l1);
    pl[i * 2 + 1] = __halves2bfloat162(l2, l3);
}

__global__ void __launch_bounds__(256) k_split_wt(const float* __restrict__ W1) {
    __shared__ float t[32][33];
    int n0 = blockIdx.x * 32, k0 = blockIdx.y * 32;
    int tx = threadIdx.x, ty = threadIdx.y;            // block (32,8)
#pragma unroll
    for (int r = 0; r < 32; r += 8)
        t[ty + r][tx] = W1[(size_t)(k0 + ty + r) * D + n0 + tx];
    __syncthreads();
#pragma unroll
    for (int r = 0; r < 32; r += 8) {
        float v = t[tx][ty + r];
        __nv_bfloat16 h = __float2bfloat16(v);
        __nv_bfloat16 l = __float2bfloat16(v - __bfloat162float(h));
        size_t o = (size_t)(n0 + ty + r) * D + k0 + tx;
        g_wt_hi[o] = h;
        g_wt_lo[o] = l;
    }
}

// ---------------------------------------------------------------------------
// s[m] = dot(x_m@W2 + b2, x_m@W3 + b3), fp32, register-tiled with smem staging.
// Block 128 threads: tx(0..15) = n index (covers W2[n=tx] and W3[n=tx]),
// ty(0..7) = 4-row group. 32 rows per CTA, 256 CTAs.
// ---------------------------------------------------------------------------
#define SROWS 32
__global__ void __launch_bounds__(128) s6_s_kernel(
    const float* __restrict__ x,
    const float* __restrict__ W2, const float* __restrict__ b2,
    const float* __restrict__ W3, const float* __restrict__ b3)
{
    __shared__ float xs[SROWS][68];
    __shared__ float ws2[64][16];
    __shared__ float ws3[64][16];
    const int tid = threadIdx.x;
    const int tx = tid & 15, ty = tid >> 4;
    const int row0 = blockIdx.x * SROWS;

    float accB[4] = {0.f, 0.f, 0.f, 0.f};
    float accC[4] = {0.f, 0.f, 0.f, 0.f};

    for (int kc = 0; kc < D; kc += 64) {
        // stage x: 32 rows x 64 k
#pragma unroll
        for (int p = 0; p < 4; p++) {
            int idx = p * 128 + tid;        // 0..511 float4s
            int r = idx >> 4, q = idx & 15;
            float4 v = *(const float4*)(x + (size_t)(row0 + r) * D + kc + q * 4);
            *(float4*)&xs[r][q * 4] = v;
        }
        // stage W2/W3 chunk: 64 x 16 each
#pragma unroll
        for (int p = 0; p < 2; p++) {
            int idx = p * 128 + tid;        // 0..255 float4s
            int r = idx >> 2, q = idx & 3;
            *(float4*)&ws2[r][q * 4] = *(const float4*)(W2 + (size_t)(kc + r) * NSTATE + q * 4);
            *(float4*)&ws3[r][q * 4] = *(const float4*)(W3 + (size_t)(kc + r) * NSTATE + q * 4);
        }
        __syncthreads();

#pragma unroll 4
        for (int k = 0; k < 64; k++) {
            float w2 = ws2[k][tx];
            float w3 = ws3[k][tx];
#pragma unroll
            for (int i = 0; i < 4; i++) {
                float xv = xs[4 * ty + i][k];
                accB[i] = fmaf(xv, w2, accB[i]);
                accC[i] = fmaf(xv, w3, accC[i]);
            }
        }
        __syncthreads();
    }

    float b2v = __ldg(b2 + tx), b3v = __ldg(b3 + tx);
#pragma unroll
    for (int i = 0; i < 4; i++) {
        float p = (accB[i] + b2v) * (accC[i] + b3v);
        p += __shfl_xor_sync(0xffffffffu, p, 1);
        p += __shfl_xor_sync(0xffffffffu, p, 2);
        p += __shfl_xor_sync(0xffffffffu, p, 4);
        p += __shfl_xor_sync(0xffffffffu, p, 8);
        if (tx == 0) g_s[row0 + 4 * ty + i] = p;
    }
}

// ---------------------------------------------------------------------------
// Main GEMM: split-bf16 x3 (K=2304) via mma.sync m16n8k16 + cp.async pipeline.
// CTA 128x128, BK=64, 3 stages, 8 warps (warp tile 64x32).
// Fused epilogue: y = x * softplus(acc + b1) * s[m].
// ---------------------------------------------------------------------------
__device__ __forceinline__ void gemm_load_stage(uint32_t sbase, int stage, int kt,
                                                int tid, int row0, int col0)
{
    const int term = kt / 12;
    const int k0 = (kt % 12) * BK;
    const __nv_bfloat16* Asrc = (term == 2) ? g_x_lo : g_x_hi;
    const __nv_bfloat16* Bsrc = (term == 1) ? g_wt_lo : g_wt_hi;
    uint32_t sa = sbase + stage * STAGE_BYTES;
    uint32_t sb = sa + ASTAGE;
#pragma unroll
    for (int c = 0; c < 4; c++) {
        int i = c * 256 + tid;          // 16B chunk 0..1023
        int r = i >> 3;                 // tile row 0..127
        int cw = i & 7;                 // chunk within 128B row
        cp_async16(sa + SW128(i * 16), Asrc + (size_t)(row0 + r) * D + k0 + cw * 8);
        cp_async16(sb + SW128(i * 16), Bsrc + (size_t)(col0 + r) * D + k0 + cw * 8);
    }
    asm volatile("cp.async.commit_group;" ::: "memory");
}

__global__ void __launch_bounds__(256, 2) s6_mma_gemm(
    const float* __restrict__ x, const float* __restrict__ b1, float* __restrict__ y)
{
    extern __shared__ __align__(1024) char smem[];
    const uint32_t sbase = smem_u32(smem);
    const int tid = threadIdx.x;
    const int wid = tid >> 5, lane = tid & 31;
    const int warp_m = wid & 1;        // 2 m-blocks of 64
    const int warp_n = wid >> 1;       // 4 n-blocks of 32
    const int row0 = blockIdx.y * BM;
    const int col0 = blockIdx.x * BN;

    float acc[4][4][4];
#pragma unroll
    for (int mi = 0; mi < 4; mi++)
#pragma unroll
        for (int ni = 0; ni < 4; ni++)
#pragma unroll
            for (int q = 0; q < 4; q++) acc[mi][ni][q] = 0.f;

    gemm_load_stage(sbase, 0, 0, tid, row0, col0);
    gemm_load_stage(sbase, 1, 1, tid, row0, col0);

    // ldmatrix address precompute (per-thread, invariant across tiles)
    const int a_m = warp_m * 64 + (lane & 15);   // + mi*16
    const int a_kc = lane >> 4;                  // + 2*ks
    const int b_n = warp_n * 32 + lane;

    for (int kt = 0; kt < KTILES; kt++) {
        const int s = kt % NSTG;
        if (kt < KTILES - 1)
            asm volatile("cp.async.wait_group 1;" ::: "memory");
        else
            asm volatile("cp.async.wait_group 0;" ::: "memory");
        __syncthreads();

        const int nx = kt + 2;
        if (nx < KTILES) gemm_load_stage(sbase, nx % NSTG, nx, tid, row0, col0);

        const uint32_t sa = sbase + s * STAGE_BYTES;
        const uint32_t sb = sa + ASTAGE;
#pragma unroll
        for (int ks = 0; ks < 4; ks++) {
            uint32_t a[4][4];
#pragma unroll
            for (int mi = 0; mi < 4; mi++) {
                int m = a_m + mi * 16;
                int kc = ks * 2 + a_kc;
                ldmatrix_x4(a[mi][0], a[mi][1], a[mi][2], a[mi][3],
                            sa + SW128(m * 128 + kc * 16));
            }
            uint32_t b0[4], b1r[4];
            ldmatrix_x4(b0[0], b0[1], b0[2], b0[3],
                        sb + SW128(b_n * 128 + (ks * 2) * 16));
            ldmatrix_x4(b1r[0], b1r[1], b1r[2], b1r[3],
                        sb + SW128(b_n * 128 + (ks * 2 + 1) * 16));
#pragma unroll
            for (int mi = 0; mi < 4; mi++)
#pragma unroll
                for (int ni = 0; ni < 4; ni++)
                    mma_bf16(acc[mi][ni],
                             a[mi][0], a[mi][1], a[mi][2], a[mi][3],
                             b0[ni], b1r[ni]);
        }
    }

    // Fused epilogue
    const int mbase = row0 + warp_m * 64;
    const int nbase = col0 + warp_n * 32;
#pragma unroll
    for (int mi = 0; mi < 4; mi++) {
        const int ma = mbase + mi * 16 + (lane >> 2);
        const int mb = ma + 8;
        const float s_a = g_s[ma];
        const float s_b = g_s[mb];
#pragma unroll
        for (int ni = 0; ni < 4; ni++) {
            const int n = nbase + ni * 8 + (lane & 3) * 2;
            float2 bb = *(const float2*)(b1 + n);
            float2 xa = *(const float2*)(x + (size_t)ma * D + n);
            float2 xb = *(const float2*)(x + (size_t)mb * D + n);
            float2 oa, ob;
            oa.x = xa.x * softplus_f(acc[mi][ni][0] + bb.x) * s_a;
            oa.y = xa.y * softplus_f(acc[mi][ni][1] + bb.y) * s_a;
            ob.x = xb.x * softplus_f(acc[mi][ni][2] + bb.x) * s_b;
            ob.y = xb.y * softplus_f(acc[mi][ni][3] + bb.y) * s_b;
            *(float2*)(y + (size_t)ma * D + n) = oa;
            *(float2*)(y + (size_t)mb * D + n) = ob;
        }
    }
}

// ---------------------------------------------------------------------------
// Launch. Inputs: x, W1, b1, W2, b2, W3, b3, A (A unused since h0 = 0).
// ---------------------------------------------------------------------------
extern "C" void kernel_launch(void* const* d_in, const int* in_sizes, int n_in,
                              void* d_out, int out_size)
{
    const float* x  = (const float*)d_in[0];
    const float* W1 = (const float*)d_in[1];
    const float* b1 = (const float*)d_in[2];
    const float* W2 = (const float*)d_in[3];
    const float* b2 = (const float*)d_in[4];
    const float* W3 = (const float*)d_in[5];
    const float* b3 = (const float*)d_in[6];
    float* y = (float*)d_out;

    static bool attr_set = false;
    if (!attr_set) {
        cudaFuncSetAttribute(s6_mma_gemm,
                             cudaFuncAttributeMaxDynamicSharedMemorySize, GEMM_SMEM);
        attr_set = true;
    }

    k_split_x<<<(M_TOTAL * D / 4) / 256, 256>>>((const float4*)x);
    k_split_wt<<<dim3(D / 32, D / 32), dim3(32, 8)>>>(W1);
    s6_s_kernel<<<M_TOTAL / SROWS, 128>>>(x, W2, b2, W3, b3);

    dim3 grid(D / BN, M_TOTAL / BM);   // (6, 64) = 384 CTAs
    s6_mma_gemm<<<grid, 256, GEMM_SMEM>>>(x, b1, y);
}

// round 4
// speedup vs baseline: 2.7948x; 1.0046x over previous
#include <cuda_runtime.h>
#include <cuda_bf16.h>
#include <stdint.h>
#include <math.h>

#define M_TOTAL 8192
#define D 768
#define NSTATE 16

// GEMM tiling
#define BM 128
#define BN 128
#define BK 64
#define NSTG 3
#define KTILES 36                 // 3 terms * (768/64)
#define ASTAGE (BM * BK * 2)      // 16384 B
#define STAGE_BYTES (2 * ASTAGE)  // 32768 B
#define GEMM_SMEM (NSTG * STAGE_BYTES)  // 98304 B

// ---------------- device scratch (no allocs allowed) ----------------
__device__ __align__(16) __nv_bfloat16 g_x_hi[M_TOTAL * D];
__device__ __align__(16) __nv_bfloat16 g_x_lo[M_TOTAL * D];
__device__ __align__(16) __nv_bfloat16 g_wt_hi[D * D];   // W1^T: [n][k]
__device__ __align__(16) __nv_bfloat16 g_wt_lo[D * D];
__device__ float g_s[M_TOTAL];

// ---------------- helpers ----------------
__device__ __forceinline__ uint32_t smem_u32(const void* p) {
    uint32_t a;
    asm("{ .reg .u64 t; cvta.to.shared.u64 t, %1; cvt.u32.u64 %0, t; }"
        : "=r"(a) : "l"(p));
    return a;
}
#define SW128(o) ((o) ^ (((o) >> 3) & 0x70))

__device__ __forceinline__ void cp_async16(uint32_t dst, const void* src) {
    asm volatile("cp.async.cg.shared.global [%0], [%1], 16;" :: "r"(dst), "l"(src));
}

__device__ __forceinline__ void ldmatrix_x4(uint32_t& r0, uint32_t& r1,
                                            uint32_t& r2, uint32_t& r3,
                                            uint32_t addr) {
    asm volatile("ldmatrix.sync.aligned.m8n8.x4.shared.b16 {%0,%1,%2,%3}, [%4];"
                 : "=r"(r0), "=r"(r1), "=r"(r2), "=r"(r3) : "r"(addr));
}

__device__ __forceinline__ void mma_bf16(float* c,
                                         uint32_t a0, uint32_t a1, uint32_t a2, uint32_t a3,
                                         uint32_t b0, uint32_t b1) {
    asm volatile("mma.sync.aligned.m16n8k16.row.col.f32.bf16.bf16.f32 "
                 "{%0,%1,%2,%3}, {%4,%5,%6,%7}, {%8,%9}, {%0,%1,%2,%3};"
                 : "+f"(c[0]), "+f"(c[1]), "+f"(c[2]), "+f"(c[3])
                 : "r"(a0), "r"(a1), "r"(a2), "r"(a3), "r"(b0), "r"(b1));
}

__device__ __forceinline__ float softplus_f(float z) {
    if (z > 20.f) return z;
    return log1pf(__expf(z));
}

// ---------------------------------------------------------------------------
// Fused prep: split x into (hi, lo) bf16 AND compute
// s[m] = dot(x_m@W2 + b2, x_m@W3 + b3) in one pass over x.
// 256 CTAs x 256 threads; CTA covers 32 rows. Thread (row, tg): tg in 0..7
// owns n = {2tg, 2tg+1}; reduce over tg by warp shuffles.
// ---------------------------------------------------------------------------
#define PR 32
__global__ void __launch_bounds__(256) k_prep(
    const float* __restrict__ x,
    const float* __restrict__ W2, const float* __restrict__ b2,
    const float* __restrict__ W3, const float* __restrict__ b3)
{
    __shared__ float xs[PR][132];
    __shared__ float w2s[128][16];
    __shared__ float w3s[128][16];

    const int tid = threadIdx.x;
    const int row0 = blockIdx.x * PR;
    const int tg = tid & 7;          // n-group
    const int row = tid >> 3;        // 0..31

    float aB0 = 0.f, aB1 = 0.f, aC0 = 0.f, aC1 = 0.f;

    for (int kc = 0; kc < D; kc += 128) {
        // Stage x chunk (32 x 128) + emit hi/lo splits.
#pragma unroll
        for (int p = 0; p < 4; p++) {
            int idx = p * 256 + tid;          // 0..1023 float4s
            int r = idx >> 5, q = idx & 31;
            size_t go = (size_t)(row0 + r) * D + kc + q * 4;
            float4 v = *(const float4*)(x + go);
            __nv_bfloat16 h0 = __float2bfloat16(v.x);
            __nv_bfloat16 h1 = __float2bfloat16(v.y);
            __nv_bfloat16 h2 = __float2bfloat16(v.z);
            __nv_bfloat16 h3 = __float2bfloat16(v.w);
            __nv_bfloat162* ph = (__nv_bfloat162*)(g_x_hi + go);
            __nv_bfloat162* pl = (__nv_bfloat162*)(g_x_lo + go);
            ph[0] = __halves2bfloat162(h0, h1);
            ph[1] = __halves2bfloat162(h2, h3);
            pl[0] = __halves2bfloat162(__float2bfloat16(v.x - __bfloat162float(h0)),
                                       __float2bfloat16(v.y - __bfloat162float(h1)));
            pl[1] = __halves2bfloat162(__float2bfloat16(v.z - __bfloat162float(h2)),
                                       __float2bfloat16(v.w - __bfloat162float(h3)));
            *(float4*)&xs[r][q * 4] = v;
        }
        // Stage W2/W3 chunk (128 x 16 each).
#pragma unroll
        for (int p = 0; p < 2; p++) {
            int idx = p * 256 + tid;          // 0..511 float4s
            int r = idx >> 2, q = idx & 3;
            *(float4*)&w2s[r][q * 4] = *(const float4*)(W2 + (size_t)(kc + r) * NSTATE + q * 4);
            *(float4*)&w3s[r][q * 4] = *(const float4*)(W3 + (size_t)(kc + r) * NSTATE + q * 4);
        }
        __syncthreads();

#pragma unroll 8
        for (int k = 0; k < 128; k++) {
            float xv = xs[row][k];
            float2 w2 = *(const float2*)&w2s[k][tg * 2];
            float2 w3 = *(const float2*)&w3s[k][tg * 2];
            aB0 = fmaf(xv, w2.x, aB0);
            aB1 = fmaf(xv, w2.y, aB1);
            aC0 = fmaf(xv, w3.x, aC0);
            aC1 = fmaf(xv, w3.y, aC1);
        }
        __syncthreads();
    }

    float p = (aB0 + __ldg(b2 + tg * 2)) * (aC0 + __ldg(b3 + tg * 2))
            + (aB1 + __ldg(b2 + tg * 2 + 1)) * (aC1 + __ldg(b3 + tg * 2 + 1));
    p += __shfl_xor_sync(0xffffffffu, p, 1);
    p += __shfl_xor_sync(0xffffffffu, p, 2);
    p += __shfl_xor_sync(0xffffffffu, p, 4);
    if (tg == 0) g_s[row0 + row] = p;
}

// ---------------------------------------------------------------------------
// W1 transpose + split.
// ---------------------------------------------------------------------------
__global__ void __launch_bounds__(256) k_split_wt(const float* __restrict__ W1) {
    __shared__ float t[32][33];
    int n0 = blockIdx.x * 32, k0 = blockIdx.y * 32;
    int tx = threadIdx.x, ty = threadIdx.y;            // block (32,8)
#pragma unroll
    for (int r = 0; r < 32; r += 8)
        t[ty + r][tx] = W1[(size_t)(k0 + ty + r) * D + n0 + tx];
    __syncthreads();
#pragma unroll
    for (int r = 0; r < 32; r += 8) {
        float v = t[tx][ty + r];
        __nv_bfloat16 h = __float2bfloat16(v);
        __nv_bfloat16 l = __float2bfloat16(v - __bfloat162float(h));
        size_t o = (size_t)(n0 + ty + r) * D + k0 + tx;
        g_wt_hi[o] = h;
        g_wt_lo[o] = l;
    }
}

// ---------------------------------------------------------------------------
// Main GEMM: split-bf16 x3 (K=2304) via mma.sync m16n8k16 + cp.async pipeline.
// CTA 128x128, BK=64, 3 stages, 8 warps (warp tile 64x32).
// Fused epilogue: y = x * softplus(acc + b1) * s[m].
// ---------------------------------------------------------------------------
__global__ void __launch_bounds__(256, 2) s6_mma_gemm(
    const float* __restrict__ x, const float* __restrict__ b1, float* __restrict__ y)
{
    extern __shared__ __align__(1024) char smem[];
    const uint32_t sbase = smem_u32(smem);
    const int tid = threadIdx.x;
    const int wid = tid >> 5, lane = tid & 31;
    const int warp_m = wid & 1;        // 2 m-blocks of 64
    const int warp_n = wid >> 1;       // 4 n-blocks of 32
    const int row0 = blockIdx.y * BM;
    const int col0 = blockIdx.x * BN;

    // -------- precomputed per-thread cp.async addressing (32-bit) --------
    // chunk index i = c*256 + tid; r = i>>3, cw = i&7. Four chunks c=0..3.
    // src byte offset within matrix: (tile_row0 + r)*D*2 + cw*16 (+ k0*2 per kt)
    // dst smem offset within stage:  SW128(i*16)  (A), + ASTAGE (B)
    uint32_t dsts[4], srcA[4], srcB[4];
#pragma unroll
    for (int c = 0; c < 4; c++) {
        int i = c * 256 + tid;
        int r = i >> 3, cw = i & 7;
        dsts[c] = SW128((uint32_t)(i * 16));
        srcA[c] = (uint32_t)(row0 + r) * (D * 2) + cw * 16;
        srcB[c] = (uint32_t)(col0 + r) * (D * 2) + cw * 16;
    }
    const char* const xhi = (const char*)g_x_hi;
    const char* const xlo = (const char*)g_x_lo;
    const char* const whi = (const char*)g_wt_hi;
    const char* const wlo = (const char*)g_wt_lo;

    // -------- precomputed ldmatrix addressing --------
    // A: m = warp_m*64 + (lane&15) + mi*16 ; kc16 = ks*32 + (lane>>4)*16
    // addr = stageA + m*128 + (kc16 ^ ((m<<4)&0x70))
    uint32_t Abase[4], Amask[4];
#pragma unroll
    for (int mi = 0; mi < 4; mi++) {
        int m = warp_m * 64 + (lane & 15) + mi * 16;
        Abase[mi] = (uint32_t)(m * 128);
        Amask[mi] = (uint32_t)((m << 4) & 0x70);
    }
    const uint32_t akb = (uint32_t)((lane >> 4) * 16);
    const int bn = warp_n * 32 + lane;
    const uint32_t Bbase = (uint32_t)(bn * 128);
    const uint32_t Bmask = (uint32_t)((bn << 4) & 0x70);

    float acc[4][4][4];
#pragma unroll
    for (int mi = 0; mi < 4; mi++)
#pragma unroll
        for (int ni = 0; ni < 4; ni++)
#pragma unroll
            for (int q = 0; q < 4; q++) acc[mi][ni][q] = 0.f;

    // -------- tile loader (cheap addressing) --------
    auto load_tile = [&](int kt, uint32_t stage_off) {
        // term: 0,1 -> x_hi ; 2 -> x_lo.  B: term 1 -> wt_lo else wt_hi.
        const char* Ab = (kt >= 24) ? xlo : xhi;
        const char* Bb = (kt >= 12 && kt < 24) ? wlo : whi;
        int ktm = kt >= 24 ? kt - 24 : (kt >= 12 ? kt - 12 : kt);
        uint32_t k0b = (uint32_t)(ktm * (BK * 2));
        uint32_t sa = sbase + stage_off;
        uint32_t sb = sa + ASTAGE;
#pragma unroll
        for (int c = 0; c < 4; c++) {
            cp_async16(sa + dsts[c], Ab + srcA[c] + k0b);
            cp_async16(sb + dsts[c], Bb + srcB[c] + k0b);
        }
        asm volatile("cp.async.commit_group;" ::: "memory");
    };

    load_tile(0, 0);
    load_tile(1, STAGE_BYTES);

#pragma unroll 3
    for (int kt = 0; kt < KTILES; kt++) {
        const uint32_t soff = (uint32_t)(kt % NSTG) * STAGE_BYTES;
        if (kt < KTILES - 1)
            asm volatile("cp.async.wait_group 1;" ::: "memory");
        else
            asm volatile("cp.async.wait_group 0;" ::: "memory");
        __syncthreads();

        const int nx = kt + 2;
        if (nx < KTILES) load_tile(nx, (uint32_t)(nx % NSTG) * STAGE_BYTES);

        const uint32_t sa = sbase + soff;
        const uint32_t sb = sa + ASTAGE;
#pragma unroll
        for (int ks = 0; ks < 4; ks++) {
            const uint32_t kk = (uint32_t)(ks * 32);
            uint32_t b0[4], b1r[4];
            ldmatrix_x4(b0[0], b0[1], b0[2], b0[3],
                        sb + Bbase + ((kk) ^ Bmask));
            ldmatrix_x4(b1r[0], b1r[1], b1r[2], b1r[3],
                        sb + Bbase + ((kk + 16) ^ Bmask));
            uint32_t a[4][4];
#pragma unroll
            for (int mi = 0; mi < 4; mi++)
                ldmatrix_x4(a[mi][0], a[mi][1], a[mi][2], a[mi][3],
                            sa + Abase[mi] + ((kk + akb) ^ Amask[mi]));
#pragma unroll
            for (int mi = 0; mi < 4; mi++)
#pragma unroll
                for (int ni = 0; ni < 4; ni++)
                    mma_bf16(acc[mi][ni],
                             a[mi][0], a[mi][1], a[mi][2], a[mi][3],
                             b0[ni], b1r[ni]);
        }
    }

    // Fused epilogue
    const int mbase = row0 + warp_m * 64;
    const int nbase = col0 + warp_n * 32;
#pragma unroll
    for (int mi = 0; mi < 4; mi++) {
        const int ma = mbase + mi * 16 + (lane >> 2);
        const int mb = ma + 8;
        const float s_a = g_s[ma];
        const float s_b = g_s[mb];
#pragma unroll
        for (int ni = 0; ni < 4; ni++) {
            const int n = nbase + ni * 8 + (lane & 3) * 2;
            float2 bb = *(const float2*)(b1 + n);
            float2 xa = *(const float2*)(x + (size_t)ma * D + n);
            float2 xb = *(const float2*)(x + (size_t)mb * D + n);
            float2 oa, ob;
            oa.x = xa.x * softplus_f(acc[mi][ni][0] + bb.x) * s_a;
            oa.y = xa.y * softplus_f(acc[mi][ni][1] + bb.y) * s_a;
            ob.x = xb.x * softplus_f(acc[mi][ni][2] + bb.x) * s_b;
            ob.y = xb.y * softplus_f(acc[mi][ni][3] + bb.y) * s_b;
            *(float2*)(y + (size_t)ma * D + n) = oa;
            *(float2*)(y + (size_t)mb * D + n) = ob;
        }
    }
}

// ---------------------------------------------------------------------------
// Launch. Inputs: x, W1, b1, W2, b2, W3, b3, A (A unused since h0 = 0).
// ---------------------------------------------------------------------------
extern "C" void kernel_launch(void* const* d_in, const int* in_sizes, int n_in,
                              void* d_out, int out_size)
{
    const float* x  = (const float*)d_in[0];
    const float* W1 = (const float*)d_in[1];
    const float* b1 = (const float*)d_in[2];
    const float* W2 = (const float*)d_in[3];
    const float* b2 = (const float*)d_in[4];
    const float* W3 = (const float*)d_in[5];
    const float* b3 = (const float*)d_in[6];
    float* y = (float*)d_out;

    static bool attr_set = false;
    if (!attr_set) {
        cudaFuncSetAttribute(s6_mma_gemm,
                             cudaFuncAttributeMaxDynamicSharedMemorySize, GEMM_SMEM);
        attr_set = true;
    }

    k_split_wt<<<dim3(D / 32, D / 32), dim3(32, 8)>>>(W1);
    k_prep<<<M_TOTAL / PR, 256>>>(x, W2, b2, W3, b3);

    dim3 grid(D / BN, M_TOTAL / BM);   // (6, 64) = 384 CTAs
    s6_mma_gemm<<<grid, 256, GEMM_SMEM>>>(x, b1, y);
}